// round 1
// baseline (speedup 1.0000x reference)
#include <cuda_runtime.h>

#define N_NODES 100000
#define D 128
#define N_EDGES 1600000

// Scratch: Y = x @ W  (51.2 MB, __device__ global per allocation rules)
__device__ float g_Y[(size_t)N_NODES * D];

// ---------------------------------------------------------------------------
// Zero the output buffer (d_out is poisoned by the harness).
// ---------------------------------------------------------------------------
__global__ void __launch_bounds__(256) zero_kernel(float4* __restrict__ z) {
    size_t i = (size_t)blockIdx.x * blockDim.x + threadIdx.x;
    z[i] = make_float4(0.f, 0.f, 0.f, 0.f);
}

// ---------------------------------------------------------------------------
// GEMM: Y = x @ W   (x: [N_NODES, 128], W: [128, 128])
// Block = 256 threads, 32 rows per block. Each warp owns 4 rows
// (warp, warp+8, warp+16, warp+24); each lane owns 4 consecutive columns.
// Per k per warp: 1 LDG.128 of W (L1-resident) + 4 LDS broadcast + 16 FFMA
//   -> FFMA issue-bound (~21 slots vs 32 FFMA-rt cycles).
// ---------------------------------------------------------------------------
constexpr int BR = 32;

__global__ void __launch_bounds__(256) gemm_kernel(const float* __restrict__ x,
                                                   const float* __restrict__ w) {
    __shared__ float xs[BR][D];
    const int row0 = blockIdx.x * BR;

    // Load 32x128 tile of x (1024 float4 by 256 threads = 4 each)
    const float4* xin = (const float4*)(x + (size_t)row0 * D);
    float4* xs4 = (float4*)xs;
#pragma unroll
    for (int i = 0; i < (BR * D / 4) / 256; i++)
        xs4[threadIdx.x + i * 256] = xin[threadIdx.x + i * 256];
    __syncthreads();

    const int lane = threadIdx.x & 31;
    const int warp = threadIdx.x >> 5;

    float4 acc0 = make_float4(0.f, 0.f, 0.f, 0.f);
    float4 acc1 = acc0, acc2 = acc0, acc3 = acc0;

    const float* x0 = xs[warp];
    const float* x1 = xs[warp + 8];
    const float* x2 = xs[warp + 16];
    const float* x3 = xs[warp + 24];
    const float4* wrow = (const float4*)w + lane;  // W[k][lane*4 .. +3]

#pragma unroll 8
    for (int k = 0; k < D; k++) {
        float4 wv = wrow[k * 32];
        float a0 = x0[k], a1 = x1[k], a2 = x2[k], a3 = x3[k];
        acc0.x += a0 * wv.x; acc0.y += a0 * wv.y; acc0.z += a0 * wv.z; acc0.w += a0 * wv.w;
        acc1.x += a1 * wv.x; acc1.y += a1 * wv.y; acc1.z += a1 * wv.z; acc1.w += a1 * wv.w;
        acc2.x += a2 * wv.x; acc2.y += a2 * wv.y; acc2.z += a2 * wv.z; acc2.w += a2 * wv.w;
        acc3.x += a3 * wv.x; acc3.y += a3 * wv.y; acc3.z += a3 * wv.z; acc3.w += a3 * wv.w;
    }

    float4* yout = (float4*)g_Y;
    yout[(size_t)(row0 + warp)      * 32 + lane] = acc0;
    yout[(size_t)(row0 + warp + 8)  * 32 + lane] = acc1;
    yout[(size_t)(row0 + warp + 16) * 32 + lane] = acc2;
    yout[(size_t)(row0 + warp + 24) * 32 + lane] = acc3;
}

// ---------------------------------------------------------------------------
// Scatter: Z[dst] += val * Y[src]   — one warp per edge.
// Lane l gathers Y[src][4l..4l+3] as float4 (coalesced 512B row read, L2-hit),
// then 4 atomicAdds to Z[dst] (coalesced across the warp -> RED.F32 to 4
// consecutive 128B lines).
// ---------------------------------------------------------------------------
__global__ void __launch_bounds__(256) scatter_kernel(const int*   __restrict__ src,
                                                      const int*   __restrict__ dst,
                                                      const float* __restrict__ val,
                                                      float*       __restrict__ z) {
    const int e = (int)(((size_t)blockIdx.x * blockDim.x + threadIdx.x) >> 5);
    if (e >= N_EDGES) return;
    const int lane = threadIdx.x & 31;

    const int   s = __ldg(src + e);
    const int   d = __ldg(dst + e);
    const float v = __ldg(val + e);

    float4 m = ((const float4*)(g_Y + (size_t)s * D))[lane];
    float* zr = z + (size_t)d * D + lane * 4;
    atomicAdd(zr + 0, v * m.x);
    atomicAdd(zr + 1, v * m.y);
    atomicAdd(zr + 2, v * m.z);
    atomicAdd(zr + 3, v * m.w);
}

// ---------------------------------------------------------------------------
// Launch
// ---------------------------------------------------------------------------
extern "C" void kernel_launch(void* const* d_in, const int* in_sizes, int n_in,
                              void* d_out, int out_size) {
    const float* x   = (const float*)d_in[0];
    const float* w   = (const float*)d_in[1];
    const int*   src = (const int*)  d_in[2];
    const int*   dst = (const int*)  d_in[3];
    const float* val = (const float*)d_in[4];
    float*       z   = (float*)d_out;

    // out_size = N_NODES * D = 12.8M floats = 3.2M float4
    zero_kernel<<<(N_NODES * D / 4) / 256, 256>>>((float4*)z);
    gemm_kernel<<<N_NODES / BR, 256>>>(x, w);
    scatter_kernel<<<((size_t)N_EDGES * 32) / 256, 256>>>(src, dst, val, z);
}

// round 2
// speedup vs baseline: 1.7033x; 1.7033x over previous
#include <cuda_runtime.h>

#define N_NODES 100000
#define D 128
#define N_EDGES 1600000

// Scratch: Y = x @ W  (51.2 MB, __device__ global per allocation rules)
__device__ float g_Y[(size_t)N_NODES * D];

// ---------------------------------------------------------------------------
// Zero the output buffer (d_out is poisoned by the harness).
// ---------------------------------------------------------------------------
__global__ void __launch_bounds__(256) zero_kernel(float4* __restrict__ z) {
    size_t i = (size_t)blockIdx.x * blockDim.x + threadIdx.x;
    z[i] = make_float4(0.f, 0.f, 0.f, 0.f);
}

// ---------------------------------------------------------------------------
// GEMM: Y = x @ W   (x: [N_NODES, 128], W: [128, 128])
// Block = 256 threads, 32 rows per block. Each warp owns 4 rows
// (warp, warp+8, warp+16, warp+24); each lane owns 4 consecutive columns.
// ---------------------------------------------------------------------------
constexpr int BR = 32;

__global__ void __launch_bounds__(256) gemm_kernel(const float* __restrict__ x,
                                                   const float* __restrict__ w) {
    __shared__ float xs[BR][D];
    const int row0 = blockIdx.x * BR;

    const float4* xin = (const float4*)(x + (size_t)row0 * D);
    float4* xs4 = (float4*)xs;
#pragma unroll
    for (int i = 0; i < (BR * D / 4) / 256; i++)
        xs4[threadIdx.x + i * 256] = xin[threadIdx.x + i * 256];
    __syncthreads();

    const int lane = threadIdx.x & 31;
    const int warp = threadIdx.x >> 5;

    float4 acc0 = make_float4(0.f, 0.f, 0.f, 0.f);
    float4 acc1 = acc0, acc2 = acc0, acc3 = acc0;

    const float* x0 = xs[warp];
    const float* x1 = xs[warp + 8];
    const float* x2 = xs[warp + 16];
    const float* x3 = xs[warp + 24];
    const float4* wrow = (const float4*)w + lane;  // W[k][lane*4 .. +3]

#pragma unroll 8
    for (int k = 0; k < D; k++) {
        float4 wv = wrow[k * 32];
        float a0 = x0[k], a1 = x1[k], a2 = x2[k], a3 = x3[k];
        acc0.x += a0 * wv.x; acc0.y += a0 * wv.y; acc0.z += a0 * wv.z; acc0.w += a0 * wv.w;
        acc1.x += a1 * wv.x; acc1.y += a1 * wv.y; acc1.z += a1 * wv.z; acc1.w += a1 * wv.w;
        acc2.x += a2 * wv.x; acc2.y += a2 * wv.y; acc2.z += a2 * wv.z; acc2.w += a2 * wv.w;
        acc3.x += a3 * wv.x; acc3.y += a3 * wv.y; acc3.z += a3 * wv.z; acc3.w += a3 * wv.w;
    }

    float4* yout = (float4*)g_Y;
    yout[(size_t)(row0 + warp)      * 32 + lane] = acc0;
    yout[(size_t)(row0 + warp + 8)  * 32 + lane] = acc1;
    yout[(size_t)(row0 + warp + 16) * 32 + lane] = acc2;
    yout[(size_t)(row0 + warp + 24) * 32 + lane] = acc3;
}

// ---------------------------------------------------------------------------
// Vector reduction: one red.global.add.v4.f32 instead of 4 scalar atomicAdds.
// Same bytes to L2, 4x fewer REDG instructions (sm_90+ PTX).
// ---------------------------------------------------------------------------
__device__ __forceinline__ void red_add_v4(float* ptr, float a, float b,
                                           float c, float d) {
    asm volatile("red.global.add.v4.f32 [%0], {%1, %2, %3, %4};"
                 :: "l"(ptr), "f"(a), "f"(b), "f"(c), "f"(d)
                 : "memory");
}

// ---------------------------------------------------------------------------
// Scatter: Z[dst] += val * Y[src]   — one warp per edge.
// Lane l gathers Y[src][4l..4l+3] as float4 (coalesced 512B row read, L2-hit),
// then one vector red.v4.f32 to Z[dst] (warp covers 4 consecutive 128B lines).
// ---------------------------------------------------------------------------
__global__ void __launch_bounds__(256) scatter_kernel(const int*   __restrict__ src,
                                                      const int*   __restrict__ dst,
                                                      const float* __restrict__ val,
                                                      float*       __restrict__ z) {
    const int e = (int)(((size_t)blockIdx.x * blockDim.x + threadIdx.x) >> 5);
    if (e >= N_EDGES) return;
    const int lane = threadIdx.x & 31;

    const int   s = __ldg(src + e);
    const int   d = __ldg(dst + e);
    const float v = __ldg(val + e);

    float4 m = ((const float4*)(g_Y + (size_t)s * D))[lane];
    float* zr = z + (size_t)d * D + lane * 4;
    red_add_v4(zr, v * m.x, v * m.y, v * m.z, v * m.w);
}

// ---------------------------------------------------------------------------
// Launch
// ---------------------------------------------------------------------------
extern "C" void kernel_launch(void* const* d_in, const int* in_sizes, int n_in,
                              void* d_out, int out_size) {
    const float* x   = (const float*)d_in[0];
    const float* w   = (const float*)d_in[1];
    const int*   src = (const int*)  d_in[2];
    const int*   dst = (const int*)  d_in[3];
    const float* val = (const float*)d_in[4];
    float*       z   = (float*)d_out;

    zero_kernel<<<(N_NODES * D / 4) / 256, 256>>>((float4*)z);
    gemm_kernel<<<N_NODES / BR, 256>>>(x, w);
    scatter_kernel<<<((size_t)N_EDGES * 32) / 256, 256>>>(src, dst, val, z);
}